// round 2
// baseline (speedup 1.0000x reference)
#include <cuda_runtime.h>
#include <cstdint>

#define SEQ 2048
#define DM  1024          // d_model
#define HD  2048          // H * 128 (projection output cols)
#define NH  16
#define HS  128           // head size

typedef unsigned long long u64;

// -------- device scratch (no allocations allowed) --------
__device__ float g_Q[SEQ * HD];      // compacted masked rows
__device__ float g_K[SEQ * HD];      // compacted masked rows
__device__ float g_V[SEQ * HD];      // all rows
__device__ float g_vmean[HD];
__device__ unsigned long long g_key[NH * SEQ];   // (orderable score << 32) | orig_t
__device__ int g_list[SEQ];          // compact idx -> original row
__device__ int g_pos[SEQ];           // original row -> compact idx
__device__ int g_maskv[SEQ];
__device__ int g_count;

__device__ __forceinline__ unsigned fkey(float f) {
    unsigned u = __float_as_uint(f);
    return (u & 0x80000000u) ? ~u : (u ^ 0x80000000u);   // ascending float -> ascending uint
}

// packed f32x2 helpers (FFMA2 is PTX-only; ptxas never auto-fuses it)
__device__ __forceinline__ u64 pk2(float x) {
    u64 r; asm("mov.b64 %0,{%1,%1};" : "=l"(r) : "f"(x)); return r;
}
__device__ __forceinline__ void fma2(u64& d, u64 a, u64 b) {
    asm("fma.rn.f32x2 %0,%1,%2,%0;" : "+l"(d) : "l"(a), "l"(b));
}
__device__ __forceinline__ float2 upk(u64 v) {
    float2 f; asm("mov.b64 {%0,%1},%2;" : "=f"(f.x), "=f"(f.y) : "l"(v)); return f;
}

// -------- mask scan: build compacted index list (1 warp) --------
__global__ void mask_scan_kernel(const unsigned* __restrict__ m) {
    int lane = threadIdx.x;
    unsigned vals[64];
#pragma unroll
    for (int c = 0; c < 64; c++) vals[c] = m[c * 32 + lane];
    int running = 0;
#pragma unroll
    for (int c = 0; c < 64; c++) {
        int i = c * 32 + lane;
        int v = vals[c] != 0u;
        g_maskv[i] = v;
        unsigned bal = __ballot_sync(0xffffffffu, v);
        int pos = running + __popc(bal & ((1u << lane) - 1u));
        if (v) { g_list[pos] = i; g_pos[i] = pos; }
        running += __popc(bal);
    }
    if (lane == 0) g_count = running;
}

__global__ void init_kernel() {
    int i = blockIdx.x * 256 + threadIdx.x;
    if (i < NH * SEQ) g_key[i] = 0xFFFFFFFFFFFFFFFFULL;
    if (i < HD) g_vmean[i] = 0.f;
}

// -------- fp32 SGEMM: C[M x 2048] = A[M x 1024] @ B[1024 x 2048] + bias --------
// 128x128 block tile, BK=16, 256 threads, 8x8 micro-tile (2x2 quadrants),
// register-prefetch pipeline, f32x2 packed FMA. gather!=0: A rows via g_list.
__global__ void __launch_bounds__(256) sgemm_kernel(
    const float* __restrict__ A, const float* __restrict__ B,
    const float* __restrict__ bias, float* __restrict__ C, int gather)
{
    __shared__ __align__(16) float As[16][132];
    __shared__ __align__(16) float Bs[16][128];
    const int M  = gather ? g_count : SEQ;
    const int m0 = blockIdx.y * 128;
    if (m0 >= M) return;
    const int n0  = blockIdx.x * 128;
    const int tid = threadIdx.x;
    const int tx  = tid & 15, ty = tid >> 4;
    const int lrow = tid >> 2, lc4 = tid & 3;

    const int r0 = m0 + lrow, r1 = m0 + lrow + 64;
    const bool v0r = r0 < M, v1r = r1 < M;
    const int gr0 = gather ? (v0r ? g_list[r0] : 0) : r0;
    const int gr1 = gather ? (v1r ? g_list[r1] : 0) : r1;
    const float4* A0 = (const float4*)(A + (size_t)gr0 * DM);
    const float4* A1 = (const float4*)(A + (size_t)gr1 * DM);
    const int brow = tid >> 5, bc4 = tid & 31;

    u64 acc2[8][4];
#pragma unroll
    for (int i = 0; i < 8; i++)
#pragma unroll
        for (int j = 0; j < 4; j++) acc2[i][j] = 0ULL;

    float4 pa0 = A0[lc4];
    float4 pa1 = A1[lc4];
    float4 pb0 = *(const float4*)(B + (size_t)(brow    ) * HD + n0 + bc4 * 4);
    float4 pb1 = *(const float4*)(B + (size_t)(brow + 8) * HD + n0 + bc4 * 4);

    for (int kt = 0; kt < 64; kt++) {
        As[lc4 * 4 + 0][lrow] = pa0.x; As[lc4 * 4 + 1][lrow] = pa0.y;
        As[lc4 * 4 + 2][lrow] = pa0.z; As[lc4 * 4 + 3][lrow] = pa0.w;
        As[lc4 * 4 + 0][lrow + 64] = pa1.x; As[lc4 * 4 + 1][lrow + 64] = pa1.y;
        As[lc4 * 4 + 2][lrow + 64] = pa1.z; As[lc4 * 4 + 3][lrow + 64] = pa1.w;
        *(float4*)&Bs[brow    ][bc4 * 4] = pb0;
        *(float4*)&Bs[brow + 8][bc4 * 4] = pb1;
        __syncthreads();

        if (kt < 63) {
            const int k0 = (kt + 1) * 16;
            pa0 = A0[(k0 >> 2) + lc4];
            pa1 = A1[(k0 >> 2) + lc4];
            pb0 = *(const float4*)(B + (size_t)(k0 + brow    ) * HD + n0 + bc4 * 4);
            pb1 = *(const float4*)(B + (size_t)(k0 + brow + 8) * HD + n0 + bc4 * 4);
        }

#pragma unroll
        for (int kk = 0; kk < 16; kk++) {
            float4 a0 = *(float4*)&As[kk][ty * 4];
            float4 a1 = *(float4*)&As[kk][64 + ty * 4];
            ulonglong2 q0 = *(const ulonglong2*)&Bs[kk][tx * 4];
            ulonglong2 q1 = *(const ulonglong2*)&Bs[kk][64 + tx * 4];
            u64 B2[4] = {q0.x, q0.y, q1.x, q1.y};
            float a[8] = {a0.x, a0.y, a0.z, a0.w, a1.x, a1.y, a1.z, a1.w};
#pragma unroll
            for (int i = 0; i < 8; i++) {
                u64 ai = pk2(a[i]);
#pragma unroll
                for (int j = 0; j < 4; j++) fma2(acc2[i][j], ai, B2[j]);
            }
        }
        __syncthreads();
    }

    float4 bia0 = *(const float4*)(bias + n0 + tx * 4);
    float4 bia1 = *(const float4*)(bias + n0 + 64 + tx * 4);
    float bb[8] = {bia0.x, bia0.y, bia0.z, bia0.w, bia1.x, bia1.y, bia1.z, bia1.w};
#pragma unroll
    for (int i = 0; i < 8; i++) {
        int r = m0 + ((i < 4) ? (ty * 4 + i) : (64 + ty * 4 + i - 4));
        if (r < M) {
            float2 f0 = upk(acc2[i][0]), f1 = upk(acc2[i][1]);
            float2 f2 = upk(acc2[i][2]), f3 = upk(acc2[i][3]);
            float4 o0, o1;
            o0.x = f0.x + bb[0]; o0.y = f0.y + bb[1];
            o0.z = f1.x + bb[2]; o0.w = f1.y + bb[3];
            o1.x = f2.x + bb[4]; o1.y = f2.y + bb[5];
            o1.z = f3.x + bb[6]; o1.w = f3.y + bb[7];
            *(float4*)(C + (size_t)r * HD + n0 + tx * 4)      = o0;
            *(float4*)(C + (size_t)r * HD + n0 + 64 + tx * 4) = o1;
        }
    }
}

// -------- scores + argmin: per head, scores[s,t] = q_s . k_t over 128 dims --------
// grid (stile=16, h=16, zsplit); each block: 128 compacted s x (t tiles strided by z).
// Min over t (softmax is exactly one-hot at argmin of raw score).
__global__ void __launch_bounds__(256) score_argmin_kernel() {
    const int Mc = g_count;
    const int stile = blockIdx.x;
    if (stile * 128 >= Mc) return;
    const int h = blockIdx.y;
    const float* Qh = g_Q + h * HS;
    const float* Kh = g_K + h * HS;

    __shared__ __align__(16) float Qs[16][132];
    __shared__ __align__(16) float Ks[16][132];
    __shared__ int tl[128];

    const int tid = threadIdx.x;
    const int tx = tid & 15, ty = tid >> 4;
    const int lrow = tid >> 2, lc4 = tid & 3;
    const int s0 = stile * 128;

    for (int tt = blockIdx.z; tt * 128 < Mc; tt += gridDim.z) {
        const int t0 = tt * 128;
        __syncthreads();                       // previous epilogue done with tl/smem
        if (tid < 128) tl[tid] = (t0 + tid < Mc) ? g_list[t0 + tid] : 0;

        u64 acc2[8][4];
#pragma unroll
        for (int i = 0; i < 8; i++)
#pragma unroll
            for (int j = 0; j < 4; j++) acc2[i][j] = 0ULL;

        for (int d0 = 0; d0 < HS; d0 += 16) {
            float4 qa = *(const float4*)(Qh + (size_t)(s0 + lrow     ) * HD + d0 + lc4 * 4);
            float4 qb = *(const float4*)(Qh + (size_t)(s0 + lrow + 64) * HD + d0 + lc4 * 4);
            float4 ka = *(const float4*)(Kh + (size_t)(t0 + lrow     ) * HD + d0 + lc4 * 4);
            float4 kb = *(const float4*)(Kh + (size_t)(t0 + lrow + 64) * HD + d0 + lc4 * 4);
            __syncthreads();                   // previous compute done before overwrite
            Qs[lc4 * 4 + 0][lrow] = qa.x; Qs[lc4 * 4 + 1][lrow] = qa.y;
            Qs[lc4 * 4 + 2][lrow] = qa.z; Qs[lc4 * 4 + 3][lrow] = qa.w;
            Qs[lc4 * 4 + 0][lrow + 64] = qb.x; Qs[lc4 * 4 + 1][lrow + 64] = qb.y;
            Qs[lc4 * 4 + 2][lrow + 64] = qb.z; Qs[lc4 * 4 + 3][lrow + 64] = qb.w;
            Ks[lc4 * 4 + 0][lrow] = ka.x; Ks[lc4 * 4 + 1][lrow] = ka.y;
            Ks[lc4 * 4 + 2][lrow] = ka.z; Ks[lc4 * 4 + 3][lrow] = ka.w;
            Ks[lc4 * 4 + 0][lrow + 64] = kb.x; Ks[lc4 * 4 + 1][lrow + 64] = kb.y;
            Ks[lc4 * 4 + 2][lrow + 64] = kb.z; Ks[lc4 * 4 + 3][lrow + 64] = kb.w;
            __syncthreads();
#pragma unroll
            for (int kk = 0; kk < 16; kk++) {
                float4 a0 = *(float4*)&Qs[kk][ty * 4];
                float4 a1 = *(float4*)&Qs[kk][64 + ty * 4];
                ulonglong2 q0 = *(const ulonglong2*)&Ks[kk][tx * 4];
                ulonglong2 q1 = *(const ulonglong2*)&Ks[kk][64 + tx * 4];
                u64 B2[4] = {q0.x, q0.y, q1.x, q1.y};
                float a[8] = {a0.x, a0.y, a0.z, a0.w, a1.x, a1.y, a1.z, a1.w};
#pragma unroll
                for (int i = 0; i < 8; i++) {
                    u64 ai = pk2(a[i]);
#pragma unroll
                    for (int j = 0; j < 4; j++) fma2(acc2[i][j], ai, B2[j]);
                }
            }
        }

        // per-row argmin epilogue
#pragma unroll
        for (int i = 0; i < 8; i++) {
            int csrow = s0 + ((i < 4) ? (ty * 4 + i) : (64 + ty * 4 + i - 4));
            float2 f0 = upk(acc2[i][0]), f1 = upk(acc2[i][1]);
            float2 f2 = upk(acc2[i][2]), f3 = upk(acc2[i][3]);
            float accv[8] = {f0.x, f0.y, f1.x, f1.y, f2.x, f2.y, f3.x, f3.y};
            float vmin = 1e30f;
            int tmin = 0;
#pragma unroll
            for (int j = 0; j < 8; j++) {
                int cl = (j < 4) ? (tx * 4 + j) : (64 + tx * 4 + j - 4);
                if (t0 + cl < Mc && accv[j] < vmin) { vmin = accv[j]; tmin = tl[cl]; }
            }
            unsigned long long key =
                ((unsigned long long)fkey(vmin) << 32) | (unsigned)tmin;
#pragma unroll
            for (int m = 1; m < 16; m <<= 1) {
                unsigned long long o = __shfl_xor_sync(0xffffffffu, key, m);
                if (o < key) key = o;
            }
            if (tx == 0 && csrow < Mc)
                atomicMin(&g_key[h * SEQ + csrow], key);
        }
    }
}

// -------- column mean of V (for unmasked rows: uniform softmax) --------
// grid (HD/256, 32): each block sums 64 rows for 256 cols, atomics to g_vmean.
__global__ void vmean_kernel() {
    int c = blockIdx.x * 256 + threadIdx.x;
    int t0 = blockIdx.y * 64;
    float s = 0.f;
#pragma unroll 8
    for (int t = t0; t < t0 + 64; t++) s += g_V[(size_t)t * HD + c];
    atomicAdd(&g_vmean[c], s * (1.0f / SEQ));
}

// -------- output assembly: one block per sequence row --------
__global__ void output_kernel(float* __restrict__ out) {
    const int s = blockIdx.x;
    const int tid = threadIdx.x;               // 256 threads, 8 floats each
    if (!g_maskv[s]) {
        float4 a = ((const float4*)g_vmean)[tid * 2];
        float4 b = ((const float4*)g_vmean)[tid * 2 + 1];
        ((float4*)(out + (size_t)s * HD))[tid * 2]     = a;
        ((float4*)(out + (size_t)s * HD))[tid * 2 + 1] = b;
    } else {
        const int cs = g_pos[s];
        const int h = tid >> 4;                // tid*8 / 128
        const int t = (int)(unsigned)(g_key[h * SEQ + cs] & 0xFFFFFFFFULL);
        const float4* src = (const float4*)(g_V + (size_t)t * HD);
        float4 a = src[tid * 2];
        float4 b = src[tid * 2 + 1];
        ((float4*)(out + (size_t)s * HD))[tid * 2]     = a;
        ((float4*)(out + (size_t)s * HD))[tid * 2 + 1] = b;
    }
}

// -------- launch --------
extern "C" void kernel_launch(void* const* d_in, const int* in_sizes, int n_in,
                              void* d_out, int out_size)
{
    const float*    X    = (const float*)d_in[0];
    const unsigned* mask = (const unsigned*)d_in[1];   // bool as f32 or i32: bits!=0
    const float*    Wq   = (const float*)d_in[2];
    const float*    bq   = (const float*)d_in[3];
    const float*    Wk   = (const float*)d_in[4];
    const float*    bk   = (const float*)d_in[5];
    const float*    Wv   = (const float*)d_in[6];
    const float*    bv   = (const float*)d_in[7];
    float* out = (float*)d_out;

    float* dQ = nullptr; float* dK = nullptr; float* dV = nullptr;
    cudaGetSymbolAddress((void**)&dQ, g_Q);
    cudaGetSymbolAddress((void**)&dK, g_K);
    cudaGetSymbolAddress((void**)&dV, g_V);

    mask_scan_kernel<<<1, 32>>>(mask);
    init_kernel<<<(NH * SEQ + 255) / 256, 256>>>();

    dim3 gg(HD / 128, SEQ / 128);              // (16, 16)
    sgemm_kernel<<<gg, 256>>>(X, Wq, bq, dQ, 1);   // masked rows only
    sgemm_kernel<<<gg, 256>>>(X, Wk, bk, dK, 1);   // masked rows only
    sgemm_kernel<<<gg, 256>>>(X, Wv, bv, dV, 0);   // all rows

    vmean_kernel<<<dim3(HD / 256, 32), 256>>>();

    dim3 gs(16, NH, 4);
    score_argmin_kernel<<<gs, 256>>>();

    output_kernel<<<SEQ, 256>>>(out);
}

// round 3
// speedup vs baseline: 1.2209x; 1.2209x over previous
#include <cuda_runtime.h>
#include <cstdint>

#define SEQ 2048
#define DM  1024          // d_model
#define HD  2048          // H * 128 (projection output cols)
#define NH  16
#define HS  128           // head size

typedef unsigned long long u64;

// -------- device scratch (no allocations allowed) --------
__device__ float g_Q[SEQ * HD];      // compacted masked rows
__device__ float g_K[SEQ * HD];      // compacted masked rows
__device__ float g_V[SEQ * HD];      // scattered: only masked (original-index) rows valid
__device__ float g_vmean[HD];
__device__ float g_xsum[DM];
__device__ u64 g_key[NH * SEQ];      // (orderable score << 32) | orig_t
__device__ int g_list[SEQ];          // compact idx -> original row
__device__ int g_pos[SEQ];           // original row -> compact idx
__device__ int g_maskv[SEQ];
__device__ int g_count;

__device__ __forceinline__ unsigned fkey(float f) {
    unsigned u = __float_as_uint(f);
    return (u & 0x80000000u) ? ~u : (u ^ 0x80000000u);   // ascending float -> ascending uint
}

// packed f32x2 helpers (FFMA2 is PTX-only; ptxas never auto-fuses it)
__device__ __forceinline__ u64 pk2(float x) {
    u64 r; asm("mov.b64 %0,{%1,%1};" : "=l"(r) : "f"(x)); return r;
}
__device__ __forceinline__ void fma2(u64& d, u64 a, u64 b) {
    asm("fma.rn.f32x2 %0,%1,%2,%0;" : "+l"(d) : "l"(a), "l"(b));
}
__device__ __forceinline__ float2 upk(u64 v) {
    float2 f; asm("mov.b64 {%0,%1},%2;" : "=f"(f.x), "=f"(f.y) : "l"(v)); return f;
}

// cp.async helpers
__device__ __forceinline__ void cp16(void* dst, const void* src) {
    uint32_t d = (uint32_t)__cvta_generic_to_shared(dst);
    asm volatile("cp.async.cg.shared.global [%0], [%1], 16;" :: "r"(d), "l"(src));
}
__device__ __forceinline__ void cp_commit() { asm volatile("cp.async.commit_group;"); }
__device__ __forceinline__ void cp_wait0()  { asm volatile("cp.async.wait_group 0;"); }

// -------- mask scan: build compacted index list (1 warp) --------
__global__ void mask_scan_kernel(const unsigned* __restrict__ m) {
    int lane = threadIdx.x;
    unsigned vals[64];
#pragma unroll
    for (int c = 0; c < 64; c++) vals[c] = m[c * 32 + lane];
    int running = 0;
#pragma unroll
    for (int c = 0; c < 64; c++) {
        int i = c * 32 + lane;
        int v = vals[c] != 0u;
        g_maskv[i] = v;
        unsigned bal = __ballot_sync(0xffffffffu, v);
        int pos = running + __popc(bal & ((1u << lane) - 1u));
        if (v) { g_list[pos] = i; g_pos[i] = pos; }
        running += __popc(bal);
    }
    if (lane == 0) g_count = running;
}

__global__ void init_kernel(const float* __restrict__ bv) {
    int i = blockIdx.x * 256 + threadIdx.x;
    if (i < NH * SEQ) g_key[i] = 0xFFFFFFFFFFFFFFFFULL;
    if (i < HD) g_vmean[i] = bv[i];          // vmean accumulates on top of bias
    if (i < DM) g_xsum[i] = 0.f;
}

// -------- column sum of X (for vmean = mean(X) @ Wv + bv) --------
__global__ void xmean_kernel(const float* __restrict__ X) {
    int c = blockIdx.x * 256 + threadIdx.x;    // grid.x = 4 -> 1024 cols
    int r0 = blockIdx.y * 256;                 // grid.y = 8
    float s = 0.f;
#pragma unroll 8
    for (int r = r0; r < r0 + 256; r++) s += X[(size_t)r * DM + c];
    atomicAdd(&g_xsum[c], s);
}

// -------- vmean projection: g_vmean += (xsum/SEQ) @ Wv --------
__global__ void vproj_kernel(const float* __restrict__ Wv) {
    int c = blockIdx.x * 256 + threadIdx.x;    // grid.x = 8 -> 2048 cols
    int k0 = blockIdx.y * 256;                 // grid.y = 4
    float s = 0.f;
#pragma unroll 8
    for (int k = k0; k < k0 + 256; k++) s += g_xsum[k] * Wv[(size_t)k * HD + c];
    atomicAdd(&g_vmean[c], s * (1.0f / SEQ));
}

// -------- fused gather-SGEMM: C[Mc x 2048] = X[g_list] @ W + b --------
// blockIdx.z selects {Q,K,V}. 128x128 tile, BK=16, 256 thr, f32x2 FMA,
// double-buffered smem, cp.async for B, ONE syncthreads per k-tile.
__global__ void __launch_bounds__(256, 2) proj_kernel(
    const float* __restrict__ A,
    const float* __restrict__ Wq, const float* __restrict__ Wk, const float* __restrict__ Wv,
    const float* __restrict__ bq, const float* __restrict__ bk, const float* __restrict__ bv,
    float* __restrict__ dQ, float* __restrict__ dK, float* __restrict__ dV)
{
    __shared__ __align__(16) float As[2][16][132];
    __shared__ __align__(16) float4 Bs[2][16][32];

    const int z = blockIdx.z;
    const float* B    = (z == 0) ? Wq : (z == 1) ? Wk : Wv;
    const float* bias = (z == 0) ? bq : (z == 1) ? bk : bv;
    float* C          = (z == 0) ? dQ : (z == 1) ? dK : dV;

    const int M  = g_count;
    const int m0 = blockIdx.y * 128;
    if (m0 >= M) return;
    const int n0 = blockIdx.x * 128;
    const int tid = threadIdx.x;
    const int tx = tid & 15, ty = tid >> 4;
    const int lrow = tid >> 2, lc4 = tid & 3;

    const int r0 = m0 + lrow, r1 = r0 + 64;
    const int gr0 = g_list[r0 < M ? r0 : 0];
    const int gr1 = g_list[r1 < M ? r1 : 0];
    const float4* A0 = (const float4*)(A + (size_t)gr0 * DM);
    const float4* A1 = (const float4*)(A + (size_t)gr1 * DM);
    const int brow = tid >> 5, bcol = tid & 31;   // B chunk mapping (2 chunks/thread)

    u64 acc2[8][4];
#pragma unroll
    for (int i = 0; i < 8; i++)
#pragma unroll
        for (int j = 0; j < 4; j++) acc2[i][j] = 0ULL;

    // ---- prologue: tile 0 ----
    float4 pa0 = A0[lc4];
    float4 pa1 = A1[lc4];
    As[0][lc4 * 4 + 0][lrow] = pa0.x; As[0][lc4 * 4 + 1][lrow] = pa0.y;
    As[0][lc4 * 4 + 2][lrow] = pa0.z; As[0][lc4 * 4 + 3][lrow] = pa0.w;
    As[0][lc4 * 4 + 0][lrow + 64] = pa1.x; As[0][lc4 * 4 + 1][lrow + 64] = pa1.y;
    As[0][lc4 * 4 + 2][lrow + 64] = pa1.z; As[0][lc4 * 4 + 3][lrow + 64] = pa1.w;
    cp16(&Bs[0][brow][bcol],     B + (size_t)(brow    ) * HD + n0 + bcol * 4);
    cp16(&Bs[0][brow + 8][bcol], B + (size_t)(brow + 8) * HD + n0 + bcol * 4);
    cp_commit();

    for (int kt = 0; kt < 64; kt++) {
        const int buf = kt & 1;
        cp_wait0();
        __syncthreads();                       // tile kt visible; everyone past compute(kt-1)
        if (kt < 63) {
            const int k0 = (kt + 1) * 16;
            cp16(&Bs[buf ^ 1][brow][bcol],     B + (size_t)(k0 + brow    ) * HD + n0 + bcol * 4);
            cp16(&Bs[buf ^ 1][brow + 8][bcol], B + (size_t)(k0 + brow + 8) * HD + n0 + bcol * 4);
            cp_commit();
            pa0 = A0[(k0 >> 2) + lc4];
            pa1 = A1[(k0 >> 2) + lc4];
        }
#pragma unroll
        for (int kk = 0; kk < 16; kk++) {
            float4 a0 = *(const float4*)&As[buf][kk][ty * 4];
            float4 a1 = *(const float4*)&As[buf][kk][64 + ty * 4];
            ulonglong2 q0 = *(const ulonglong2*)&Bs[buf][kk][tx];
            ulonglong2 q1 = *(const ulonglong2*)&Bs[buf][kk][16 + tx];
            u64 B2[4] = {q0.x, q0.y, q1.x, q1.y};
            float a[8] = {a0.x, a0.y, a0.z, a0.w, a1.x, a1.y, a1.z, a1.w};
#pragma unroll
            for (int i = 0; i < 8; i++) {
                u64 ai = pk2(a[i]);
#pragma unroll
                for (int j = 0; j < 4; j++) fma2(acc2[i][j], ai, B2[j]);
            }
        }
        if (kt < 63) {
            As[buf ^ 1][lc4 * 4 + 0][lrow] = pa0.x; As[buf ^ 1][lc4 * 4 + 1][lrow] = pa0.y;
            As[buf ^ 1][lc4 * 4 + 2][lrow] = pa0.z; As[buf ^ 1][lc4 * 4 + 3][lrow] = pa0.w;
            As[buf ^ 1][lc4 * 4 + 0][lrow + 64] = pa1.x; As[buf ^ 1][lc4 * 4 + 1][lrow + 64] = pa1.y;
            As[buf ^ 1][lc4 * 4 + 2][lrow + 64] = pa1.z; As[buf ^ 1][lc4 * 4 + 3][lrow + 64] = pa1.w;
        }
    }

    float4 bia0 = *(const float4*)(bias + n0 + tx * 4);
    float4 bia1 = *(const float4*)(bias + n0 + 64 + tx * 4);
    float bb[8] = {bia0.x, bia0.y, bia0.z, bia0.w, bia1.x, bia1.y, bia1.z, bia1.w};
#pragma unroll
    for (int i = 0; i < 8; i++) {
        int rc = m0 + ((i < 4) ? (ty * 4 + i) : (64 + ty * 4 + i - 4));
        if (rc < M) {
            int rout = (z == 2) ? g_list[rc] : rc;   // V scattered to original index
            float2 f0 = upk(acc2[i][0]), f1 = upk(acc2[i][1]);
            float2 f2 = upk(acc2[i][2]), f3 = upk(acc2[i][3]);
            float4 o0, o1;
            o0.x = f0.x + bb[0]; o0.y = f0.y + bb[1];
            o0.z = f1.x + bb[2]; o0.w = f1.y + bb[3];
            o1.x = f2.x + bb[4]; o1.y = f2.y + bb[5];
            o1.z = f3.x + bb[6]; o1.w = f3.y + bb[7];
            *(float4*)(C + (size_t)rout * HD + n0 + tx * 4)      = o0;
            *(float4*)(C + (size_t)rout * HD + n0 + 64 + tx * 4) = o1;
        }
    }
}

// -------- scores + argmin: per head, min_t q_s.k_t (softmax is exact one-hot) --------
// grid (stile=16, h=16, z=4). Flat chunk pipeline: double-buffered smem,
// one syncthreads per 16-d chunk, t-tiles strided by z.
__global__ void __launch_bounds__(256, 2) score_kernel() {
    __shared__ __align__(16) float Qs[2][16][132];
    __shared__ __align__(16) float Ks[2][16][132];
    __shared__ int tl[2][128];

    const int Mc = g_count;
    const int stile = blockIdx.x;
    const int s0 = stile * 128;
    if (s0 >= Mc) return;
    const int h = blockIdx.y;
    const int z = blockIdx.z;
    const int ntiles = (Mc + 127) >> 7;
    const int nmine = (ntiles - z + 3) >> 2;
    if (nmine <= 0) return;
    const float* Qh = g_Q + h * HS;
    const float* Kh = g_K + h * HS;

    const int tid = threadIdx.x;
    const int tx = tid & 15, ty = tid >> 4;
    const int lrow = tid >> 2, lc4 = tid & 3;
    const int utot = nmine * 8;

    // ---- prologue: chunk (tile 0 = t-tile z, d=0) ----
    if (tid < 128) {
        int t = z * 128 + tid;
        tl[0][tid] = (t < Mc) ? g_list[t] : 0;
    }
    float4 qa = *(const float4*)(Qh + (size_t)(s0 + lrow     ) * HD + lc4 * 4);
    float4 qb = *(const float4*)(Qh + (size_t)(s0 + lrow + 64) * HD + lc4 * 4);
    float4 ka = *(const float4*)(Kh + (size_t)(z * 128 + lrow     ) * HD + lc4 * 4);
    float4 kb = *(const float4*)(Kh + (size_t)(z * 128 + lrow + 64) * HD + lc4 * 4);
    Qs[0][lc4 * 4 + 0][lrow] = qa.x; Qs[0][lc4 * 4 + 1][lrow] = qa.y;
    Qs[0][lc4 * 4 + 2][lrow] = qa.z; Qs[0][lc4 * 4 + 3][lrow] = qa.w;
    Qs[0][lc4 * 4 + 0][lrow + 64] = qb.x; Qs[0][lc4 * 4 + 1][lrow + 64] = qb.y;
    Qs[0][lc4 * 4 + 2][lrow + 64] = qb.z; Qs[0][lc4 * 4 + 3][lrow + 64] = qb.w;
    Ks[0][lc4 * 4 + 0][lrow] = ka.x; Ks[0][lc4 * 4 + 1][lrow] = ka.y;
    Ks[0][lc4 * 4 + 2][lrow] = ka.z; Ks[0][lc4 * 4 + 3][lrow] = ka.w;
    Ks[0][lc4 * 4 + 0][lrow + 64] = kb.x; Ks[0][lc4 * 4 + 1][lrow + 64] = kb.y;
    Ks[0][lc4 * 4 + 2][lrow + 64] = kb.z; Ks[0][lc4 * 4 + 3][lrow + 64] = kb.w;

    u64 acc2[8][4];
#pragma unroll
    for (int i = 0; i < 8; i++)
#pragma unroll
        for (int j = 0; j < 4; j++) acc2[i][j] = 0ULL;

    for (int u = 0; u < utot; u++) {
        const int buf = u & 1;
        const int it  = u >> 3;
        __syncthreads();                       // chunk u visible; compute(u-1) done everywhere
        const int un = u + 1;
        if (un < utot) {
            const int i_n = un >> 3, d_n = (un & 7) * 16;
            const int t0n = (z + i_n * 4) * 128;
            qa = *(const float4*)(Qh + (size_t)(s0 + lrow     ) * HD + d_n + lc4 * 4);
            qb = *(const float4*)(Qh + (size_t)(s0 + lrow + 64) * HD + d_n + lc4 * 4);
            ka = *(const float4*)(Kh + (size_t)(t0n + lrow     ) * HD + d_n + lc4 * 4);
            kb = *(const float4*)(Kh + (size_t)(t0n + lrow + 64) * HD + d_n + lc4 * 4);
            if ((un & 7) == 0 && tid < 128) {
                int t = t0n + tid;
                tl[i_n & 1][tid] = (t < Mc) ? g_list[t] : 0;
            }
        }
#pragma unroll
        for (int kk = 0; kk < 16; kk++) {
            float4 a0 = *(const float4*)&Qs[buf][kk][ty * 4];
            float4 a1 = *(const float4*)&Qs[buf][kk][64 + ty * 4];
            ulonglong2 q0 = *(const ulonglong2*)&Ks[buf][kk][tx * 4];
            ulonglong2 q1 = *(const ulonglong2*)&Ks[buf][kk][64 + tx * 4];
            u64 B2[4] = {q0.x, q0.y, q1.x, q1.y};
            float a[8] = {a0.x, a0.y, a0.z, a0.w, a1.x, a1.y, a1.z, a1.w};
#pragma unroll
            for (int i = 0; i < 8; i++) {
                u64 ai = pk2(a[i]);
#pragma unroll
                for (int j = 0; j < 4; j++) fma2(acc2[i][j], ai, B2[j]);
            }
        }
        if (un < utot) {
            const int nb = buf ^ 1;
            Qs[nb][lc4 * 4 + 0][lrow] = qa.x; Qs[nb][lc4 * 4 + 1][lrow] = qa.y;
            Qs[nb][lc4 * 4 + 2][lrow] = qa.z; Qs[nb][lc4 * 4 + 3][lrow] = qa.w;
            Qs[nb][lc4 * 4 + 0][lrow + 64] = qb.x; Qs[nb][lc4 * 4 + 1][lrow + 64] = qb.y;
            Qs[nb][lc4 * 4 + 2][lrow + 64] = qb.z; Qs[nb][lc4 * 4 + 3][lrow + 64] = qb.w;
            Ks[nb][lc4 * 4 + 0][lrow] = ka.x; Ks[nb][lc4 * 4 + 1][lrow] = ka.y;
            Ks[nb][lc4 * 4 + 2][lrow] = ka.z; Ks[nb][lc4 * 4 + 3][lrow] = ka.w;
            Ks[nb][lc4 * 4 + 0][lrow + 64] = kb.x; Ks[nb][lc4 * 4 + 1][lrow + 64] = kb.y;
            Ks[nb][lc4 * 4 + 2][lrow + 64] = kb.z; Ks[nb][lc4 * 4 + 3][lrow + 64] = kb.w;
        }
        if ((u & 7) == 7) {
            const int t0 = (z + it * 4) * 128;
#pragma unroll
            for (int i = 0; i < 8; i++) {
                int csrow = s0 + ((i < 4) ? (ty * 4 + i) : (64 + ty * 4 + i - 4));
                float2 f0 = upk(acc2[i][0]), f1 = upk(acc2[i][1]);
                float2 f2 = upk(acc2[i][2]), f3 = upk(acc2[i][3]);
                float accv[8] = {f0.x, f0.y, f1.x, f1.y, f2.x, f2.y, f3.x, f3.y};
                float vmin = 1e30f;
                int tmin = 0;
#pragma unroll
                for (int j = 0; j < 8; j++) {
                    int cl = (j < 4) ? (tx * 4 + j) : (64 + tx * 4 + j - 4);
                    if (t0 + cl < Mc && accv[j] < vmin) { vmin = accv[j]; tmin = tl[it & 1][cl]; }
                }
                u64 key = ((u64)fkey(vmin) << 32) | (unsigned)tmin;
#pragma unroll
                for (int m = 1; m < 16; m <<= 1) {
                    u64 o = __shfl_xor_sync(0xffffffffu, key, m);
                    if (o < key) key = o;
                }
                if (tx == 0 && csrow < Mc)
                    atomicMin(&g_key[h * SEQ + csrow], key);
                acc2[i][0] = acc2[i][1] = acc2[i][2] = acc2[i][3] = 0ULL;
            }
        }
    }
}

// -------- output assembly: one block per sequence row --------
__global__ void output_kernel(float* __restrict__ out) {
    const int s = blockIdx.x;
    const int tid = threadIdx.x;               // 256 threads, 8 floats each
    if (!g_maskv[s]) {
        float4 a = ((const float4*)g_vmean)[tid * 2];
        float4 b = ((const float4*)g_vmean)[tid * 2 + 1];
        ((float4*)(out + (size_t)s * HD))[tid * 2]     = a;
        ((float4*)(out + (size_t)s * HD))[tid * 2 + 1] = b;
    } else {
        const int cs = g_pos[s];
        const int h = tid >> 4;                // tid*8 / 128
        const int t = (int)(unsigned)(g_key[h * SEQ + cs] & 0xFFFFFFFFULL);
        const float4* src = (const float4*)(g_V + (size_t)t * HD);
        float4 a = src[tid * 2];
        float4 b = src[tid * 2 + 1];
        ((float4*)(out + (size_t)s * HD))[tid * 2]     = a;
        ((float4*)(out + (size_t)s * HD))[tid * 2 + 1] = b;
    }
}

// -------- launch --------
extern "C" void kernel_launch(void* const* d_in, const int* in_sizes, int n_in,
                              void* d_out, int out_size)
{
    const float*    X    = (const float*)d_in[0];
    const unsigned* mask = (const unsigned*)d_in[1];   // bool as f32 or i32: bits!=0
    const float*    Wq   = (const float*)d_in[2];
    const float*    bq   = (const float*)d_in[3];
    const float*    Wk   = (const float*)d_in[4];
    const float*    bk   = (const float*)d_in[5];
    const float*    Wv   = (const float*)d_in[6];
    const float*    bv   = (const float*)d_in[7];
    float* out = (float*)d_out;

    float* dQ = nullptr; float* dK = nullptr; float* dV = nullptr;
    cudaGetSymbolAddress((void**)&dQ, g_Q);
    cudaGetSymbolAddress((void**)&dK, g_K);
    cudaGetSymbolAddress((void**)&dV, g_V);

    mask_scan_kernel<<<1, 32>>>(mask);
    init_kernel<<<(NH * SEQ + 255) / 256, 256>>>(bv);

    xmean_kernel<<<dim3(DM / 256, 8), 256>>>(X);

    dim3 gg(HD / 128, SEQ / 128, 3);           // fused Q,K,V gather-GEMM
    proj_kernel<<<gg, 256>>>(X, Wq, Wk, Wv, bq, bk, bv, dQ, dK, dV);

    vproj_kernel<<<dim3(HD / 256, 4), 256>>>(Wv);

    dim3 gs(16, NH, 4);
    score_kernel<<<gs, 256>>>();

    output_kernel<<<SEQ, 256>>>(out);
}